// round 2
// baseline (speedup 1.0000x reference)
#include <cuda_runtime.h>

#define FPB     256      // features per block (threads per block)
#define NSPLIT  64       // batch splits for stats pass
#define ASPLIT  128      // batch splits for apply pass
#define MAXF    2048
#define EPS     1e-5f

// Deterministic scratch (no atomics, no allocation)
__device__ float g_part[(size_t)NSPLIT * 14 * MAXF];   // per-split partial moments
__device__ float g_accum[14 * MAXF];                   // combined moments
__device__ float g_Mc[(size_t)MAXF * 20];              // per-feature M (16) + c (4)

// ---------------------------------------------------------------------------
// Pass 1: per-feature raw moments over a batch slice.
// grid = (F/FPB, NSPLIT), block = FPB. Thread t handles feature f = bx*FPB+t.
// Coalesced: warp reads 32 consecutive float4 = 512B contiguous per row.
// ---------------------------------------------------------------------------
__global__ void k_stats(const float4* __restrict__ x, int B, int F, int rowsPer) {
    int f = blockIdx.x * FPB + threadIdx.x;
    if (f >= F) return;
    int b0 = blockIdx.y * rowsPer;
    int b1 = min(b0 + rowsPer, B);

    float a[14];
#pragma unroll
    for (int i = 0; i < 14; i++) a[i] = 0.f;

    size_t idx = (size_t)b0 * F + f;
#pragma unroll 4
    for (int b = b0; b < b1; b++, idx += F) {
        float4 v = x[idx];
        a[0] += v.x; a[1] += v.y; a[2] += v.z; a[3] += v.w;
        a[4]  = fmaf(v.x, v.x, a[4]);
        a[5]  = fmaf(v.y, v.x, a[5]);
        a[6]  = fmaf(v.y, v.y, a[6]);
        a[7]  = fmaf(v.z, v.x, a[7]);
        a[8]  = fmaf(v.z, v.y, a[8]);
        a[9]  = fmaf(v.z, v.z, a[9]);
        a[10] = fmaf(v.w, v.x, a[10]);
        a[11] = fmaf(v.w, v.y, a[11]);
        a[12] = fmaf(v.w, v.z, a[12]);
        a[13] = fmaf(v.w, v.w, a[13]);
    }

    float* p = g_part + ((size_t)blockIdx.y * 14) * F + f;
#pragma unroll
    for (int k = 0; k < 14; k++) p[(size_t)k * F] = a[k];
}

// ---------------------------------------------------------------------------
// Combine the NSPLIT partials, fixed order -> deterministic.
// ---------------------------------------------------------------------------
__global__ void k_combine(int F) {
    int i = blockIdx.x * blockDim.x + threadIdx.x;
    int tot = 14 * F;
    if (i >= tot) return;
    float s = 0.f;
#pragma unroll 8
    for (int k = 0; k < NSPLIT; k++)
        s += g_part[(size_t)k * tot + i];
    g_accum[i] = s;
}

// ---------------------------------------------------------------------------
// Per-feature: cov -> Cholesky -> L^-1 -> M = G*L^-1, c = beta - M*mean.
// ---------------------------------------------------------------------------
__global__ void k_solve(const float* __restrict__ gamma,
                        const float* __restrict__ beta, int B, int F) {
    int f = blockIdx.x * blockDim.x + threadIdx.x;
    if (f >= F) return;
    float invB = 1.f / (float)B;

    float m0 = g_accum[0 * F + f] * invB;
    float m1 = g_accum[1 * F + f] * invB;
    float m2 = g_accum[2 * F + f] * invB;
    float m3 = g_accum[3 * F + f] * invB;

    float c00 = g_accum[4  * F + f] * invB - m0 * m0 + EPS;
    float c10 = g_accum[5  * F + f] * invB - m1 * m0;
    float c11 = g_accum[6  * F + f] * invB - m1 * m1 + EPS;
    float c20 = g_accum[7  * F + f] * invB - m2 * m0;
    float c21 = g_accum[8  * F + f] * invB - m2 * m1;
    float c22 = g_accum[9  * F + f] * invB - m2 * m2 + EPS;
    float c30 = g_accum[10 * F + f] * invB - m3 * m0;
    float c31 = g_accum[11 * F + f] * invB - m3 * m1;
    float c32 = g_accum[12 * F + f] * invB - m3 * m2;
    float c33 = g_accum[13 * F + f] * invB - m3 * m3 + EPS;

    // Cholesky (lower)
    float l00 = sqrtf(c00);
    float r0  = 1.f / l00;
    float l10 = c10 * r0, l20 = c20 * r0, l30 = c30 * r0;
    float l11 = sqrtf(c11 - l10 * l10);
    float r1  = 1.f / l11;
    float l21 = (c21 - l20 * l10) * r1;
    float l31 = (c31 - l30 * l10) * r1;
    float l22 = sqrtf(c22 - l20 * l20 - l21 * l21);
    float r2  = 1.f / l22;
    float l32 = (c32 - l30 * l20 - l31 * l21) * r2;
    float l33 = sqrtf(c33 - l30 * l30 - l31 * l31 - l32 * l32);
    float r3  = 1.f / l33;

    // L^-1 (lower triangular, forward substitution against I)
    float I00 = r0;
    float I10 = -l10 * I00 * r1;
    float I11 = r1;
    float I20 = -(l20 * I00 + l21 * I10) * r2;
    float I21 = -(l21 * I11) * r2;
    float I22 = r2;
    float I30 = -(l30 * I00 + l31 * I10 + l32 * I20) * r3;
    float I31 = -(l31 * I11 + l32 * I21) * r3;
    float I32 = -(l32 * I22) * r3;
    float I33 = r3;

    // gamma tril order: (0,0)(1,0)(1,1)(2,0)(2,1)(2,2)(3,0)(3,1)(3,2)(3,3)
    const float* g = gamma + (size_t)f * 10;
    float G00 = g[0], G10 = g[1], G11 = g[2], G20 = g[3], G21 = g[4];
    float G22 = g[5], G30 = g[6], G31 = g[7], G32 = g[8], G33 = g[9];

    float R[4][4] = {{G00, G10, G20, G30},
                     {G10, G11, G21, G31},
                     {G20, G21, G22, G32},
                     {G30, G31, G32, G33}};

    float M[16];
#pragma unroll
    for (int i = 0; i < 4; i++) {
        M[i * 4 + 0] = R[i][0] * I00 + R[i][1] * I10 + R[i][2] * I20 + R[i][3] * I30;
        M[i * 4 + 1] = R[i][1] * I11 + R[i][2] * I21 + R[i][3] * I31;
        M[i * 4 + 2] = R[i][2] * I22 + R[i][3] * I32;
        M[i * 4 + 3] = R[i][3] * I33;
    }

    float* o = g_Mc + (size_t)f * 20;
    const float* bt = beta + (size_t)f * 4;
#pragma unroll
    for (int i = 0; i < 4; i++) {
#pragma unroll
        for (int j = 0; j < 4; j++) o[i * 4 + j] = M[i * 4 + j];
        o[16 + i] = bt[i] - (M[i * 4 + 0] * m0 + M[i * 4 + 1] * m1 +
                             M[i * 4 + 2] * m2 + M[i * 4 + 3] * m3);
    }
}

// ---------------------------------------------------------------------------
// Pass 2: out = M*x + c. M,c register-resident per thread (one feature per
// thread for the whole batch slice). Fully coalesced float4 load+store.
// ---------------------------------------------------------------------------
__global__ void k_apply(const float4* __restrict__ x, float4* __restrict__ out,
                        int B, int F, int rowsPer) {
    int f = blockIdx.x * FPB + threadIdx.x;
    if (f >= F) return;

    const float* mc = g_Mc + (size_t)f * 20;
    float m[16], c[4];
#pragma unroll
    for (int i = 0; i < 16; i++) m[i] = mc[i];
#pragma unroll
    for (int i = 0; i < 4; i++) c[i] = mc[16 + i];

    int b0 = blockIdx.y * rowsPer;
    int b1 = min(b0 + rowsPer, B);
    size_t idx = (size_t)b0 * F + f;
#pragma unroll 4
    for (int b = b0; b < b1; b++, idx += F) {
        float4 v = x[idx];
        float4 o;
        o.x = fmaf(m[0],  v.x, fmaf(m[1],  v.y, fmaf(m[2],  v.z, fmaf(m[3],  v.w, c[0]))));
        o.y = fmaf(m[4],  v.x, fmaf(m[5],  v.y, fmaf(m[6],  v.z, fmaf(m[7],  v.w, c[1]))));
        o.z = fmaf(m[8],  v.x, fmaf(m[9],  v.y, fmaf(m[10], v.z, fmaf(m[11], v.w, c[2]))));
        o.w = fmaf(m[12], v.x, fmaf(m[13], v.y, fmaf(m[14], v.z, fmaf(m[15], v.w, c[3]))));
        out[idx] = o;
    }
}

extern "C" void kernel_launch(void* const* d_in, const int* in_sizes, int n_in,
                              void* d_out, int out_size) {
    const float* x     = (const float*)d_in[0];
    const float* gamma = (const float*)d_in[1];
    const float* beta  = (const float*)d_in[2];

    int F = in_sizes[1] / 10;          // gamma is [F, 10]
    int B = in_sizes[0] / (F * 4);     // x is [B, F, 4]

    int fblocks = (F + FPB - 1) / FPB;

    int rowsStat = (B + NSPLIT - 1) / NSPLIT;
    dim3 gs(fblocks, NSPLIT);
    k_stats<<<gs, FPB>>>((const float4*)x, B, F, rowsStat);

    int tot = 14 * F;
    k_combine<<<(tot + 255) / 256, 256>>>(F);

    k_solve<<<(F + 255) / 256, 256>>>(gamma, beta, B, F);

    int rowsApply = (B + ASPLIT - 1) / ASPLIT;
    dim3 ga(fblocks, ASPLIT);
    k_apply<<<ga, FPB>>>((const float4*)x, (float4*)d_out, B, F, rowsApply);
}